// round 1
// baseline (speedup 1.0000x reference)
#include <cuda_runtime.h>
#include <float.h>
#include <stdint.h>
#include <stddef.h>

#define NN 50000      // nodes
#define NE 800000     // edges
#define EF 96         // edge features
#define NF 256        // node features
#define GF 64         // global features
#define HID 1024      // hidden
#define MIN_ 608      // MLP input = 256 + 3*96 + 64

// ---------------- scratch (static __device__ — no allocation allowed) -------
__device__ int   g_cnt[NN];
__device__ int   g_off[NN];
__device__ int   g_wptr[NN];
__device__ int   g_bsum[64];
__device__ int   g_bucket[NE];
__device__ float g_h[(size_t)NN * MIN_];    // 121.6 MB
__device__ float g_h1[(size_t)NN * HID];    // 204.8 MB

// ---------------- CSR build --------------------------------------------------
__global__ void k_zero() {
    int i = blockIdx.x * blockDim.x + threadIdx.x;
    if (i < NN) g_cnt[i] = 0;
}

__global__ void k_hist(const int* __restrict__ ei) {
    int e = blockIdx.x * blockDim.x + threadIdx.x;
    if (e < NE) atomicAdd(&g_cnt[ei[NE + e]], 1);
}

// per-1024-block exclusive scan (Hillis-Steele), block sums out
__global__ void k_scan1() {
    __shared__ int sh[1024];
    int i = blockIdx.x * 1024 + threadIdx.x;
    int v = (i < NN) ? g_cnt[i] : 0;
    sh[threadIdx.x] = v;
    __syncthreads();
    for (int d = 1; d < 1024; d <<= 1) {
        int t = (threadIdx.x >= (unsigned)d) ? sh[threadIdx.x - d] : 0;
        __syncthreads();
        sh[threadIdx.x] += t;
        __syncthreads();
    }
    if (i < NN) g_off[i] = sh[threadIdx.x] - v;   // exclusive
    if (threadIdx.x == 1023) g_bsum[blockIdx.x] = sh[1023];
}

// scan the (<=64) block sums, single block of 64 threads
__global__ void k_scan2(int nb) {
    __shared__ int sh[64];
    int v = ((int)threadIdx.x < nb) ? g_bsum[threadIdx.x] : 0;
    sh[threadIdx.x] = v;
    __syncthreads();
    for (int d = 1; d < 64; d <<= 1) {
        int t = (threadIdx.x >= (unsigned)d) ? sh[threadIdx.x - d] : 0;
        __syncthreads();
        sh[threadIdx.x] += t;
        __syncthreads();
    }
    if ((int)threadIdx.x < nb) g_bsum[threadIdx.x] = sh[threadIdx.x] - v;
}

__global__ void k_addoff() {
    int i = blockIdx.x * 1024 + threadIdx.x;
    if (i < NN) {
        int o = g_off[i] + g_bsum[blockIdx.x];
        g_off[i]  = o;
        g_wptr[i] = o;
    }
}

__global__ void k_bucket(const int* __restrict__ ei) {
    int e = blockIdx.x * blockDim.x + threadIdx.x;
    if (e < NE) {
        int c = ei[NE + e];
        int p = atomicAdd(&g_wptr[c], 1);
        g_bucket[p] = e;
    }
}

// ---------------- gather reduce + build h ------------------------------------
// one block (128 threads) per node: threads 0..95 own one edge-feature each,
// loop over this node's edges; block also copies x-row and u[batch[n]] into h.
__global__ void k_node(const float* __restrict__ x, const float* __restrict__ ea,
                       const float* __restrict__ u, const int* __restrict__ batch) {
    int n   = blockIdx.x;
    int tid = threadIdx.x;
    float* hrow = g_h + (size_t)n * MIN_;

    for (int i = tid; i < NF; i += 128)
        hrow[i] = x[(size_t)n * NF + i];
    if (tid < GF)
        hrow[NF + 3 * EF + tid] = u[(size_t)batch[n] * GF + tid];

    if (tid < EF) {
        int off = g_off[n];
        int deg = g_cnt[n];
        float s = 0.f, m = -FLT_MAX;
        for (int i = 0; i < deg; i++) {
            int e = g_bucket[off + i];
            float v = ea[(size_t)e * EF + tid];
            s += v;
            m = fmaxf(m, v);
        }
        if (deg == 0) m = 0.f;                      // torch_scatter empty-seg = 0
        hrow[NF + tid]          = s;                // sum
        hrow[NF + EF + tid]     = m;                // max
        hrow[NF + 2 * EF + tid] = s / fmaxf((float)deg, 1.f); // mean
    }
}

// ---------------- SGEMM 128x128x8, 8x8 per thread ----------------------------
// A: MxK row-major, B: KxN row-major, C: MxN. K % 8 == 0, N % 128 == 0.
// relu: apply relu after bias. resid: optional residual added (same layout as C).
__global__ __launch_bounds__(256) void k_sgemm(
        const float* __restrict__ A, const float* __restrict__ B,
        const float* __restrict__ bias, const float* __restrict__ resid,
        float* __restrict__ C, int M, int N, int K, int relu)
{
    __shared__ float As[8][128];
    __shared__ float Bs[8][128];
    int tid = threadIdx.x;
    int tx = tid & 15, ty = tid >> 4;
    int lrA = tid >> 1,  lcA = (tid & 1) << 2;
    int lrB = tid >> 5,  lcB = (tid & 31) << 2;
    int arow = blockIdx.y * 128 + lrA;
    const float* Ap = A + (size_t)arow * K;
    const float* Bp = B + (size_t)lrB * N + blockIdx.x * 128 + lcB;

    float acc[8][8];
#pragma unroll
    for (int i = 0; i < 8; i++)
#pragma unroll
        for (int j = 0; j < 8; j++) acc[i][j] = 0.f;

    for (int kt = 0; kt < K; kt += 8) {
        float4 av = make_float4(0.f, 0.f, 0.f, 0.f);
        if (arow < M) av = *(const float4*)(Ap + kt + lcA);
        As[lcA + 0][lrA] = av.x;
        As[lcA + 1][lrA] = av.y;
        As[lcA + 2][lrA] = av.z;
        As[lcA + 3][lrA] = av.w;
        float4 bv = *(const float4*)(Bp + (size_t)kt * N);
        *(float4*)&Bs[lrB][lcB] = bv;
        __syncthreads();
#pragma unroll
        for (int k = 0; k < 8; k++) {
            float a[8], b[8];
#pragma unroll
            for (int i = 0; i < 8; i++) a[i] = As[k][ty * 8 + i];
#pragma unroll
            for (int j = 0; j < 8; j++) b[j] = Bs[k][tx * 8 + j];
#pragma unroll
            for (int i = 0; i < 8; i++)
#pragma unroll
                for (int j = 0; j < 8; j++)
                    acc[i][j] = fmaf(a[i], b[j], acc[i][j]);
        }
        __syncthreads();
    }

    int crow0 = blockIdx.y * 128 + ty * 8;
    int ccol0 = blockIdx.x * 128 + tx * 8;
#pragma unroll
    for (int i = 0; i < 8; i++) {
        int r = crow0 + i;
        if (r < M) {
#pragma unroll
            for (int j = 0; j < 8; j++) {
                int c = ccol0 + j;
                float v = acc[i][j] + bias[c];
                if (relu) v = fmaxf(v, 0.f);
                if (resid) v += resid[(size_t)r * N + c];
                C[(size_t)r * N + c] = v;
            }
        }
    }
}

// ---------------- launch ------------------------------------------------------
extern "C" void kernel_launch(void* const* d_in, const int* in_sizes, int n_in,
                              void* d_out, int out_size) {
    const float* x     = (const float*)d_in[0];
    const float* ea    = (const float*)d_in[1];
    const float* u     = (const float*)d_in[2];
    const float* W1    = (const float*)d_in[3];
    const float* b1    = (const float*)d_in[4];
    const float* W2    = (const float*)d_in[5];
    const float* b2    = (const float*)d_in[6];
    const int*   ei    = (const int*)d_in[7];
    const int*   batch = (const int*)d_in[8];
    float*       out   = (float*)d_out;

    float *hp = nullptr, *h1p = nullptr;
    cudaGetSymbolAddress((void**)&hp,  g_h);
    cudaGetSymbolAddress((void**)&h1p, g_h1);

    int nb = (NN + 1023) / 1024;  // 49

    k_zero  <<<(NN + 255) / 256, 256>>>();
    k_hist  <<<(NE + 255) / 256, 256>>>(ei);
    k_scan1 <<<nb, 1024>>>();
    k_scan2 <<<1, 64>>>(nb);
    k_addoff<<<nb, 1024>>>();
    k_bucket<<<(NE + 255) / 256, 256>>>(ei);
    k_node  <<<NN, 128>>>(x, ea, u, batch);

    // h[50000,608] @ W1[608,1024] + b1, relu -> h1
    k_sgemm<<<dim3(HID / 128, (NN + 127) / 128), 256>>>(
        hp, W1, b1, nullptr, h1p, NN, HID, MIN_, 1);
    // h1[50000,1024] @ W2[1024,256] + b2 + x -> out
    k_sgemm<<<dim3(NF / 128, (NN + 127) / 128), 256>>>(
        h1p, W2, b2, x, out, NN, NF, HID, 0);
}

// round 3
// speedup vs baseline: 2.9402x; 2.9402x over previous
#include <cuda_runtime.h>
#include <float.h>
#include <stdint.h>
#include <stddef.h>

#define NN 50000      // nodes
#define NE 800000     // edges
#define EF 96         // edge features
#define NF 256        // node features
#define GF 64         // global features
#define HID 1024      // hidden
#define MIN_ 608      // MLP input = 256 + 3*96 + 64

// ---------------- scratch (static __device__ — no allocation allowed) -------
__device__ int   g_cnt[NN];
__device__ int   g_off[NN];
__device__ int   g_wptr[NN];
__device__ int   g_bsum[64];
__device__ int   g_bucket[NE];
__device__ float g_h[(size_t)NN * MIN_];     // 121.6 MB (tf32-rounded)
__device__ float g_h1[(size_t)NN * HID];     // 204.8 MB (tf32-rounded)
__device__ float g_w1t[(size_t)MIN_ * HID];  // tf32-rounded W1
__device__ float g_w2t[(size_t)HID * NF];    // tf32-rounded W2

__device__ __forceinline__ float tf32r(float x) {
    float y;
    asm("cvt.rna.tf32.f32 %0, %1;" : "=f"(y) : "f"(x));
    return y;
}

// ---------------- CSR build --------------------------------------------------
__global__ void k_zero() {
    int i = blockIdx.x * blockDim.x + threadIdx.x;
    if (i < NN) g_cnt[i] = 0;
}

__global__ void k_hist(const int* __restrict__ ei) {
    int e = blockIdx.x * blockDim.x + threadIdx.x;
    if (e < NE) atomicAdd(&g_cnt[ei[NE + e]], 1);
}

__global__ void k_scan1() {
    __shared__ int sh[1024];
    int i = blockIdx.x * 1024 + threadIdx.x;
    int v = (i < NN) ? g_cnt[i] : 0;
    sh[threadIdx.x] = v;
    __syncthreads();
    for (int d = 1; d < 1024; d <<= 1) {
        int t = (threadIdx.x >= (unsigned)d) ? sh[threadIdx.x - d] : 0;
        __syncthreads();
        sh[threadIdx.x] += t;
        __syncthreads();
    }
    if (i < NN) g_off[i] = sh[threadIdx.x] - v;   // exclusive
    if (threadIdx.x == 1023) g_bsum[blockIdx.x] = sh[1023];
}

__global__ void k_scan2(int nb) {
    __shared__ int sh[64];
    int v = ((int)threadIdx.x < nb) ? g_bsum[threadIdx.x] : 0;
    sh[threadIdx.x] = v;
    __syncthreads();
    for (int d = 1; d < 64; d <<= 1) {
        int t = (threadIdx.x >= (unsigned)d) ? sh[threadIdx.x - d] : 0;
        __syncthreads();
        sh[threadIdx.x] += t;
        __syncthreads();
    }
    if ((int)threadIdx.x < nb) g_bsum[threadIdx.x] = sh[threadIdx.x] - v;
}

__global__ void k_addoff() {
    int i = blockIdx.x * 1024 + threadIdx.x;
    if (i < NN) {
        int o = g_off[i] + g_bsum[blockIdx.x];
        g_off[i]  = o;
        g_wptr[i] = o;
    }
}

__global__ void k_bucket(const int* __restrict__ ei) {
    int e = blockIdx.x * blockDim.x + threadIdx.x;
    if (e < NE) {
        int c = ei[NE + e];
        int p = atomicAdd(&g_wptr[c], 1);
        g_bucket[p] = e;
    }
}

// ---------------- round weights to tf32 --------------------------------------
__global__ void k_round_w(const float* __restrict__ W1, const float* __restrict__ W2) {
    int i = blockIdx.x * blockDim.x + threadIdx.x;
    if (i < MIN_ * HID) g_w1t[i] = tf32r(W1[i]);
    if (i < HID * NF)   g_w2t[i] = tf32r(W2[i]);
}

// ---------------- gather reduce + build h (tf32-rounded) ---------------------
__global__ void k_node(const float* __restrict__ x, const float* __restrict__ ea,
                       const float* __restrict__ u, const int* __restrict__ batch) {
    int n   = blockIdx.x;
    int tid = threadIdx.x;
    float* hrow = g_h + (size_t)n * MIN_;

    for (int i = tid; i < NF; i += 128)
        hrow[i] = tf32r(x[(size_t)n * NF + i]);
    if (tid < GF)
        hrow[NF + 3 * EF + tid] = tf32r(u[(size_t)batch[n] * GF + tid]);

    if (tid < EF) {
        int off = g_off[n];
        int deg = g_cnt[n];
        float s = 0.f, m = -FLT_MAX;
        for (int i = 0; i < deg; i++) {
            int e = g_bucket[off + i];
            float v = ea[(size_t)e * EF + tid];
            s += v;
            m = fmaxf(m, v);
        }
        if (deg == 0) m = 0.f;
        hrow[NF + tid]          = tf32r(s);
        hrow[NF + EF + tid]     = tf32r(m);
        hrow[NF + 2 * EF + tid] = tf32r(s / fmaxf((float)deg, 1.f));
    }
}

// ---------------- tf32 tensor-core GEMM --------------------------------------
// C[M,N] = A[M,K] @ B[K,N] (+bias, relu?, round?, resid?)
// Block tile 128x256, BK=16, 8 warps in 2(M)x4(N), warp tile 64x64.
// mma.sync.aligned.m16n8k8.row.col.f32.tf32.tf32.f32
// Requires K % 16 == 0, N % 256 == 0.

#define AS_STRIDE 20
#define BS_STRIDE 264
#define AS_ELEMS (128 * AS_STRIDE)   // 2560
#define BS_ELEMS (16 * BS_STRIDE)    // 4224
#define BUF_ELEMS (AS_ELEMS + BS_ELEMS)
#define SMEM_BYTES (2 * BUF_ELEMS * 4)   // 54272

__device__ __forceinline__ void g2s_tile(
        const float* __restrict__ A, const float* __restrict__ B,
        float* as, float* bs, int M, int N, int K,
        int by, int bx, int kt, int tid)
{
#pragma unroll
    for (int i = 0; i < 2; i++) {           // A: 128x16 = 512 float4
        int f = tid + i * 256;
        int row = f >> 2, kk = (f & 3) << 2;
        int gr = by * 128 + row;
        if (gr >= M) gr = M - 1;            // clamp (epilogue guards writes)
        const float* src = A + (size_t)gr * K + kt * 16 + kk;
        uint32_t dst = (uint32_t)__cvta_generic_to_shared(as + row * AS_STRIDE + kk);
        asm volatile("cp.async.cg.shared.global [%0], [%1], 16;" :: "r"(dst), "l"(src));
    }
#pragma unroll
    for (int i = 0; i < 4; i++) {           // B: 16x256 = 1024 float4
        int f = tid + i * 256;
        int kr = f >> 6, n = (f & 63) << 2;
        const float* src = B + (size_t)(kt * 16 + kr) * N + bx * 256 + n;
        uint32_t dst = (uint32_t)__cvta_generic_to_shared(bs + kr * BS_STRIDE + n);
        asm volatile("cp.async.cg.shared.global [%0], [%1], 16;" :: "r"(dst), "l"(src));
    }
    asm volatile("cp.async.commit_group;");
}

template<int RELU, int ROUND_OUT, int RESID>
__global__ __launch_bounds__(256, 1) void k_gemm_tc(
        const float* __restrict__ A, const float* __restrict__ B,
        const float* __restrict__ bias, const float* __restrict__ resid,
        float* __restrict__ C, int M, int N, int K)
{
    extern __shared__ float smem[];
    int tid  = threadIdx.x;
    int lane = tid & 31;
    int warp = tid >> 5;
    int g    = lane >> 2;     // groupID
    int tig  = lane & 3;      // threadID_in_group
    int wm   = warp >> 2;     // 0..1
    int wn   = warp & 3;      // 0..3
    int by   = blockIdx.y, bx = blockIdx.x;

    float acc[4][8][4];
#pragma unroll
    for (int mi = 0; mi < 4; mi++)
#pragma unroll
        for (int ni = 0; ni < 8; ni++)
#pragma unroll
            for (int r = 0; r < 4; r++) acc[mi][ni][r] = 0.f;

    int nk = K >> 4;
    // prologue: tile 0 -> buffer 0
    g2s_tile(A, B, smem, smem + AS_ELEMS, M, N, K, by, bx, 0, tid);

    for (int kt = 0; kt < nk; kt++) {
        float* as = smem + (kt & 1) * BUF_ELEMS;
        float* bs = as + AS_ELEMS;
        if (kt + 1 < nk) {
            float* nas = smem + ((kt + 1) & 1) * BUF_ELEMS;
            g2s_tile(A, B, nas, nas + AS_ELEMS, M, N, K, by, bx, kt + 1, tid);
            asm volatile("cp.async.wait_group 1;");
        } else {
            asm volatile("cp.async.wait_group 0;");
        }
        __syncthreads();

#pragma unroll
        for (int k8 = 0; k8 < 16; k8 += 8) {
            uint32_t af[4][4], bf[8][2];
#pragma unroll
            for (int mi = 0; mi < 4; mi++) {
                int r = wm * 64 + mi * 16 + g;
                af[mi][0] = __float_as_uint(as[r * AS_STRIDE + k8 + tig]);
                af[mi][1] = __float_as_uint(as[(r + 8) * AS_STRIDE + k8 + tig]);
                af[mi][2] = __float_as_uint(as[r * AS_STRIDE + k8 + tig + 4]);
                af[mi][3] = __float_as_uint(as[(r + 8) * AS_STRIDE + k8 + tig + 4]);
            }
#pragma unroll
            for (int ni = 0; ni < 8; ni++) {
                int c = wn * 64 + ni * 8 + g;
                bf[ni][0] = __float_as_uint(bs[(k8 + tig) * BS_STRIDE + c]);
                bf[ni][1] = __float_as_uint(bs[(k8 + tig + 4) * BS_STRIDE + c]);
            }
#pragma unroll
            for (int mi = 0; mi < 4; mi++)
#pragma unroll
                for (int ni = 0; ni < 8; ni++) {
                    asm volatile(
                        "mma.sync.aligned.m16n8k8.row.col.f32.tf32.tf32.f32 "
                        "{%0,%1,%2,%3}, {%4,%5,%6,%7}, {%8,%9}, {%0,%1,%2,%3};"
                        : "+f"(acc[mi][ni][0]), "+f"(acc[mi][ni][1]),
                          "+f"(acc[mi][ni][2]), "+f"(acc[mi][ni][3])
                        : "r"(af[mi][0]), "r"(af[mi][1]), "r"(af[mi][2]), "r"(af[mi][3]),
                          "r"(bf[ni][0]), "r"(bf[ni][1]));
                }
        }
        __syncthreads();
    }

    // epilogue
#pragma unroll
    for (int mi = 0; mi < 4; mi++) {
#pragma unroll
        for (int ni = 0; ni < 8; ni++) {
            int r0 = by * 128 + wm * 64 + mi * 16 + g;
            int c0 = bx * 256 + wn * 64 + ni * 8 + tig * 2;
#pragma unroll
            for (int half = 0; half < 2; half++) {
                int r = r0 + half * 8;
                if (r < M) {
                    float v0 = acc[mi][ni][half * 2 + 0] + bias[c0];
                    float v1 = acc[mi][ni][half * 2 + 1] + bias[c0 + 1];
                    if (RELU) { v0 = fmaxf(v0, 0.f); v1 = fmaxf(v1, 0.f); }
                    if (ROUND_OUT) { v0 = tf32r(v0); v1 = tf32r(v1); }
                    if (RESID) {
                        v0 += resid[(size_t)r * N + c0];
                        v1 += resid[(size_t)r * N + c0 + 1];
                    }
                    *(float2*)(C + (size_t)r * N + c0) = make_float2(v0, v1);
                }
            }
        }
    }
}

// ---------------- launch ------------------------------------------------------
extern "C" void kernel_launch(void* const* d_in, const int* in_sizes, int n_in,
                              void* d_out, int out_size) {
    const float* x     = (const float*)d_in[0];
    const float* ea    = (const float*)d_in[1];
    const float* u     = (const float*)d_in[2];
    const float* W1    = (const float*)d_in[3];
    const float* b1    = (const float*)d_in[4];
    const float* W2    = (const float*)d_in[5];
    const float* b2    = (const float*)d_in[6];
    const int*   ei    = (const int*)d_in[7];
    const int*   batch = (const int*)d_in[8];
    float*       out   = (float*)d_out;

    float *hp = nullptr, *h1p = nullptr, *w1p = nullptr, *w2p = nullptr;
    cudaGetSymbolAddress((void**)&hp,  g_h);
    cudaGetSymbolAddress((void**)&h1p, g_h1);
    cudaGetSymbolAddress((void**)&w1p, g_w1t);
    cudaGetSymbolAddress((void**)&w2p, g_w2t);

    // Unconditional every call (no static guards — harness rule). Host-side,
    // not stream work, so graph capture is unaffected.
    cudaFuncSetAttribute(k_gemm_tc<1,1,0>, cudaFuncAttributeMaxDynamicSharedMemorySize, SMEM_BYTES);
    cudaFuncSetAttribute(k_gemm_tc<0,0,1>, cudaFuncAttributeMaxDynamicSharedMemorySize, SMEM_BYTES);

    int nb = (NN + 1023) / 1024;  // 49

    k_zero   <<<(NN + 255) / 256, 256>>>();
    k_hist   <<<(NE + 255) / 256, 256>>>(ei);
    k_scan1  <<<nb, 1024>>>();
    k_scan2  <<<1, 64>>>(nb);
    k_addoff <<<nb, 1024>>>();
    k_bucket <<<(NE + 255) / 256, 256>>>(ei);
    k_round_w<<<(MIN_ * HID + 255) / 256, 256>>>(W1, W2);
    k_node   <<<NN, 128>>>(x, ea, u, batch);

    // h[50000,608] @ W1t[608,1024] + b1, relu, round -> h1
    k_gemm_tc<1,1,0><<<dim3(HID / 256, (NN + 127) / 128), 256, SMEM_BYTES>>>(
        hp, w1p, b1, nullptr, h1p, NN, HID, MIN_);
    // h1[50000,1024] @ W2t[1024,256] + b2 + x -> out
    k_gemm_tc<0,0,1><<<dim3(NF / 256, (NN + 127) / 128), 256, SMEM_BYTES>>>(
        h1p, w2p, b2, x, out, NN, NF, HID);
}

// round 5
// speedup vs baseline: 4.3893x; 1.4928x over previous
#include <cuda_runtime.h>
#include <cuda_fp16.h>
#include <float.h>
#include <stdint.h>
#include <stddef.h>

#define NN 50000      // nodes
#define NE 800000     // edges
#define EF 96         // edge features
#define NF 256        // node features
#define GF 64         // global features
#define HID 1024      // hidden
#define MIN_ 608      // MLP input = 256 + 3*96 + 64

// ---------------- scratch (static __device__ — no allocation allowed) -------
__device__ int    g_cnt[NN];
__device__ int    g_off[NN];
__device__ int    g_wptr[NN];
__device__ int    g_bsum[64];
__device__ int    g_bucket[NE];
__device__ __align__(128) __half g_h[(size_t)NN * MIN_];    // fp16 MLP input
__device__ __align__(128) __half g_h1[(size_t)NN * HID];    // fp16 hidden
__device__ __align__(128) __half g_w1t[(size_t)HID * MIN_]; // W1^T [1024][608]
__device__ __align__(128) __half g_w2t[(size_t)NF * HID];   // W2^T [256][1024]

// ---------------- CSR build --------------------------------------------------
__global__ void k_zero() {
    int i = blockIdx.x * blockDim.x + threadIdx.x;
    if (i < NN) g_cnt[i] = 0;
}
__global__ void k_hist(const int* __restrict__ ei) {
    int e = blockIdx.x * blockDim.x + threadIdx.x;
    if (e < NE) atomicAdd(&g_cnt[ei[NE + e]], 1);
}
__global__ void k_scan1() {
    __shared__ int sh[1024];
    int i = blockIdx.x * 1024 + threadIdx.x;
    int v = (i < NN) ? g_cnt[i] : 0;
    sh[threadIdx.x] = v;
    __syncthreads();
    for (int d = 1; d < 1024; d <<= 1) {
        int t = (threadIdx.x >= (unsigned)d) ? sh[threadIdx.x - d] : 0;
        __syncthreads();
        sh[threadIdx.x] += t;
        __syncthreads();
    }
    if (i < NN) g_off[i] = sh[threadIdx.x] - v;
    if (threadIdx.x == 1023) g_bsum[blockIdx.x] = sh[1023];
}
__global__ void k_scan2(int nb) {
    __shared__ int sh[64];
    int v = ((int)threadIdx.x < nb) ? g_bsum[threadIdx.x] : 0;
    sh[threadIdx.x] = v;
    __syncthreads();
    for (int d = 1; d < 64; d <<= 1) {
        int t = (threadIdx.x >= (unsigned)d) ? sh[threadIdx.x - d] : 0;
        __syncthreads();
        sh[threadIdx.x] += t;
        __syncthreads();
    }
    if ((int)threadIdx.x < nb) g_bsum[threadIdx.x] = sh[threadIdx.x] - v;
}
__global__ void k_addoff() {
    int i = blockIdx.x * 1024 + threadIdx.x;
    if (i < NN) {
        int o = g_off[i] + g_bsum[blockIdx.x];
        g_off[i]  = o;
        g_wptr[i] = o;
    }
}
__global__ void k_bucket(const int* __restrict__ ei) {
    int e = blockIdx.x * blockDim.x + threadIdx.x;
    if (e < NE) {
        int c = ei[NE + e];
        int p = atomicAdd(&g_wptr[c], 1);
        g_bucket[p] = e;
    }
}

// ---------------- transpose + convert weights to fp16 ------------------------
__global__ void k_prep_w(const float* __restrict__ W1, const float* __restrict__ W2) {
    int idx = blockIdx.x * blockDim.x + threadIdx.x;
    if (idx < HID * MIN_) {
        int n = idx / MIN_, k = idx % MIN_;
        g_w1t[idx] = __float2half(W1[(size_t)k * HID + n]);
    }
    if (idx < NF * HID) {
        int n = idx / HID, k = idx % HID;
        g_w2t[idx] = __float2half(W2[(size_t)k * NF + n]);
    }
}

// ---------------- gather reduce + build h (fp16) -----------------------------
__global__ void k_node(const float* __restrict__ x, const float* __restrict__ ea,
                       const float* __restrict__ u, const int* __restrict__ batch) {
    int n   = blockIdx.x;
    int tid = threadIdx.x;
    __half* hrow = g_h + (size_t)n * MIN_;

    for (int i = tid; i < NF; i += 128)
        hrow[i] = __float2half(x[(size_t)n * NF + i]);
    if (tid < GF)
        hrow[NF + 3 * EF + tid] = __float2half(u[(size_t)batch[n] * GF + tid]);

    if (tid < EF) {
        int off = g_off[n];
        int deg = g_cnt[n];
        float s = 0.f, m = -FLT_MAX;
#pragma unroll 4
        for (int i = 0; i < deg; i++) {
            int e = __ldg(&g_bucket[off + i]);
            float v = __ldg(&ea[(size_t)e * EF + tid]);
            s += v;
            m = fmaxf(m, v);
        }
        if (deg == 0) m = 0.f;
        hrow[NF + tid]          = __float2half(s);
        hrow[NF + EF + tid]     = __float2half(m);
        hrow[NF + 2 * EF + tid] = __float2half(s / fmaxf((float)deg, 1.f));
    }
}

// ---------------- fp16 tensor-core GEMM --------------------------------------
// C[M,Ntot] = A[M,K](fp16) @ Bt[Ntot,K](fp16)^T, fp32 accumulate.
// BM=128, BN=256, BK=32, 8 warps (2Mx4N), warp tile 64x64.
// mma.sync.aligned.m16n8k16.row.col.f32.f16.f16.f32
// smem: A [128][40] halves, B [256][40] halves per stage, triple-buffered.
#define HSTRIDE   40                 // halves per row (pad 8) -> 20 words
#define A_BYTES   (128 * HSTRIDE * 2)   // 10240
#define B_BYTES   (256 * HSTRIDE * 2)   // 20480
#define STAGE_B   (A_BYTES + B_BYTES)   // 30720
#define G_SMEM    (3 * STAGE_B)         // 92160

__device__ __forceinline__ void cpa16(uint32_t dst, const void* src) {
    asm volatile("cp.async.cg.shared.global [%0], [%1], 16;" :: "r"(dst), "l"(src));
}
__device__ __forceinline__ uint32_t smem_u32(const void* p) {
    uint32_t a;
    asm("{ .reg .u64 t; cvta.to.shared.u64 t, %1; cvt.u32.u64 %0, t; }" : "=r"(a) : "l"(p));
    return a;
}

__device__ __forceinline__ void store2(__half* C, size_t idx, float v0, float v1) {
    *(__half2*)(C + idx) = __floats2half2_rn(v0, v1);
}
__device__ __forceinline__ void store2(float* C, size_t idx, float v0, float v1) {
    *(float2*)(C + idx) = make_float2(v0, v1);
}

template<int RELU, int RESID, typename TO>
__global__ __launch_bounds__(256) void k_gemm_h(
        const __half* __restrict__ A, const __half* __restrict__ Bt,
        const float* __restrict__ bias, const float* __restrict__ resid,
        TO* __restrict__ C, int M, int Ntot, int K)
{
    extern __shared__ __align__(128) char smem[];
    uint32_t sb = smem_u32(smem);
    int tid  = threadIdx.x;
    int lane = tid & 31;
    int warp = tid >> 5;
    int g    = lane >> 2;     // groupID 0..7
    int tig  = lane & 3;      // thread-in-group 0..3
    int wm   = warp >> 2;     // 0..1
    int wn   = warp & 3;      // 0..3
    int bx = blockIdx.x, by = blockIdx.y;

    float acc[4][8][4];
#pragma unroll
    for (int mi = 0; mi < 4; mi++)
#pragma unroll
        for (int ni = 0; ni < 8; ni++)
#pragma unroll
            for (int r = 0; r < 4; r++) acc[mi][ni][r] = 0.f;

    int nk = K >> 5;   // K / 32

    // tile loader: A 128 rows x 64B (4 chunks), B 256 rows x 64B
    auto load_tile = [&](int kt, int s) {
        uint32_t base = sb + s * STAGE_B;
#pragma unroll
        for (int i = 0; i < 2; i++) {
            int f = tid + i * 256;
            int row = f >> 2, cb = f & 3;
            int gr = by * 128 + row;
            if (gr >= M) gr = M - 1;
            cpa16(base + row * (HSTRIDE * 2) + cb * 16,
                  A + (size_t)gr * K + kt * 32 + cb * 8);
        }
#pragma unroll
        for (int i = 0; i < 4; i++) {
            int f = tid + i * 256;
            int row = f >> 2, cb = f & 3;
            cpa16(base + A_BYTES + row * (HSTRIDE * 2) + cb * 16,
                  Bt + (size_t)(bx * 256 + row) * K + kt * 32 + cb * 8);
        }
        asm volatile("cp.async.commit_group;");
    };

    load_tile(0, 0);
    if (nk > 1) load_tile(1, 1);
    int s = 0;
    for (int t = 0; t < nk; t++) {
        if (t + 1 < nk) asm volatile("cp.async.wait_group 1;");
        else            asm volatile("cp.async.wait_group 0;");
        __syncthreads();

        const uint32_t* asw = (const uint32_t*)(smem + s * STAGE_B);
        const uint32_t* bsw = (const uint32_t*)(smem + s * STAGE_B + A_BYTES);
#pragma unroll
        for (int ks = 0; ks < 2; ks++) {            // two k16 steps
            int ko = ks * 8;                        // word offset
            uint32_t af[4][4], bf[8][2];
#pragma unroll
            for (int mi = 0; mi < 4; mi++) {
                int r = wm * 64 + mi * 16 + g;
                af[mi][0] = asw[r * 20 + ko + tig];
                af[mi][1] = asw[(r + 8) * 20 + ko + tig];
                af[mi][2] = asw[r * 20 + ko + 4 + tig];
                af[mi][3] = asw[(r + 8) * 20 + ko + 4 + tig];
            }
#pragma unroll
            for (int ni = 0; ni < 8; ni++) {
                int c = wn * 64 + ni * 8 + g;
                bf[ni][0] = bsw[c * 20 + ko + tig];
                bf[ni][1] = bsw[c * 20 + ko + 4 + tig];
            }
#pragma unroll
            for (int mi = 0; mi < 4; mi++)
#pragma unroll
                for (int ni = 0; ni < 8; ni++) {
                    asm volatile(
                        "mma.sync.aligned.m16n8k16.row.col.f32.f16.f16.f32 "
                        "{%0,%1,%2,%3}, {%4,%5,%6,%7}, {%8,%9}, {%0,%1,%2,%3};"
                        : "+f"(acc[mi][ni][0]), "+f"(acc[mi][ni][1]),
                          "+f"(acc[mi][ni][2]), "+f"(acc[mi][ni][3])
                        : "r"(af[mi][0]), "r"(af[mi][1]), "r"(af[mi][2]), "r"(af[mi][3]),
                          "r"(bf[ni][0]), "r"(bf[ni][1]));
                }
        }
        __syncthreads();
        if (t + 2 < nk) load_tile(t + 2, (s + 2) % 3);
        s = (s + 1) % 3;
    }

    // epilogue
#pragma unroll
    for (int mi = 0; mi < 4; mi++) {
#pragma unroll
        for (int ni = 0; ni < 8; ni++) {
            int r0 = by * 128 + wm * 64 + mi * 16 + g;
            int c0 = bx * 256 + wn * 64 + ni * 8 + tig * 2;
            float bv0 = bias[c0], bv1 = bias[c0 + 1];
#pragma unroll
            for (int hh = 0; hh < 2; hh++) {
                int r = r0 + hh * 8;
                if (r < M) {
                    float v0 = acc[mi][ni][hh * 2 + 0] + bv0;
                    float v1 = acc[mi][ni][hh * 2 + 1] + bv1;
                    if (RELU) { v0 = fmaxf(v0, 0.f); v1 = fmaxf(v1, 0.f); }
                    size_t base = (size_t)r * Ntot + c0;
                    if (RESID) {
                        float2 rr = *(const float2*)(resid + base);
                        v0 += rr.x; v1 += rr.y;
                    }
                    store2(C, base, v0, v1);
                }
            }
        }
    }
}

// ---------------- launch ------------------------------------------------------
extern "C" void kernel_launch(void* const* d_in, const int* in_sizes, int n_in,
                              void* d_out, int out_size) {
    const float* x     = (const float*)d_in[0];
    const float* ea    = (const float*)d_in[1];
    const float* u     = (const float*)d_in[2];
    const float* W1    = (const float*)d_in[3];
    const float* b1    = (const float*)d_in[4];
    const float* W2    = (const float*)d_in[5];
    const float* b2    = (const float*)d_in[6];
    const int*   ei    = (const int*)d_in[7];
    const int*   batch = (const int*)d_in[8];
    float*       out   = (float*)d_out;

    __half *hp = nullptr, *h1p = nullptr, *w1p = nullptr, *w2p = nullptr;
    cudaGetSymbolAddress((void**)&hp,  g_h);
    cudaGetSymbolAddress((void**)&h1p, g_h1);
    cudaGetSymbolAddress((void**)&w1p, g_w1t);
    cudaGetSymbolAddress((void**)&w2p, g_w2t);

    cudaFuncSetAttribute(k_gemm_h<1,0,__half>, cudaFuncAttributeMaxDynamicSharedMemorySize, G_SMEM);
    cudaFuncSetAttribute(k_gemm_h<0,1,float>,  cudaFuncAttributeMaxDynamicSharedMemorySize, G_SMEM);

    int nb = (NN + 1023) / 1024;  // 49

    k_zero   <<<(NN + 255) / 256, 256>>>();
    k_hist   <<<(NE + 255) / 256, 256>>>(ei);
    k_scan1  <<<nb, 1024>>>();
    k_scan2  <<<1, 64>>>(nb);
    k_addoff <<<nb, 1024>>>();
    k_bucket <<<(NE + 255) / 256, 256>>>(ei);
    k_prep_w <<<(HID * MIN_ + 255) / 256, 256>>>(W1, W2);
    k_node   <<<NN, 128>>>(x, ea, u, batch);

    // h[50000,608] @ W1 + b1, relu -> h1 (fp16)
    k_gemm_h<1,0,__half><<<dim3(HID / 256, (NN + 127) / 128), 256, G_SMEM>>>(
        hp, w1p, b1, nullptr, h1p, NN, HID, MIN_);
    // h1[50000,1024] @ W2 + b2 + x -> out (fp32)
    k_gemm_h<0,1,float><<<dim3(NF / 256, (NN + 127) / 128), 256, G_SMEM>>>(
        h1p, w2p, b2, x, out, NN, NF, HID);
}